// round 2
// baseline (speedup 1.0000x reference)
#include <cuda_runtime.h>
#include <math.h>

// Problem constants
#define BSZ   2048
#define INSZ  512
#define HSZ   512
#define OUTSZ 256
#define NSZ   32768
#define H3    (3*HSZ)
#define T_MAX 48

// ---------------- device scratch (static, no allocations) ----------------
__device__ float d_h0[BSZ*HSZ];
__device__ float d_h1[BSZ*HSZ];
__device__ float d_A0[BSZ*H3];
__device__ float d_G0[BSZ*H3];
__device__ float d_G1b[BSZ*H3];
__device__ float d_A1[BSZ*H3];
__device__ float d_Y1[(size_t)T_MAX*BSZ*HSZ];
__device__ int   d_first[BSZ];
__device__ int   d_rowoff[NSZ];
__device__ int   d_T[1];

// ---------------- setup kernels ----------------
__global__ void k_init() {
    int i = blockIdx.x * blockDim.x + threadIdx.x;
    if (i == 0) d_T[0] = 0;
    if (i < BSZ*HSZ) { d_h0[i] = 0.f; d_h1[i] = 0.f; }
}

__global__ void k_first(const int* __restrict__ psi) {
    int j = blockIdx.x * blockDim.x + threadIdx.x;
    if (j >= NSZ) return;
    if (j == 0 || psi[j] != psi[j-1]) d_first[psi[j]] = j;
}

__global__ void k_rank(const int* __restrict__ psi) {
    int j = blockIdx.x * blockDim.x + threadIdx.x;
    if (j >= NSZ) return;
    int v = psi[j];
    int r = j - d_first[v];
    d_rowoff[j] = r * (BSZ*HSZ) + v * HSZ;   // element offset of row start in d_Y1
    atomicMax(&d_T[0], r + 1);
}

// ---------------- TF32 mma GEMM: C[M,N] = A[M,K] * W[N,K]^T (+bias) ----------------
// A rows optionally indirected through a_off (element offset of row start).
#define BM 128
#define BN 128
#define BK 32
#define SST 136   // smem row stride (conflict-free: 136 mod 32 == 8)

__global__ __launch_bounds__(256, 2)
void gemm_tf32(const float* __restrict__ A, const float* __restrict__ W,
               float* __restrict__ C, int M, int N, int K,
               const int* __restrict__ a_off, const float* __restrict__ bias,
               int t_step, int check_T)
{
    if (check_T && t_step >= d_T[0]) return;

    __shared__ unsigned int As[BK * SST];
    __shared__ unsigned int Ws[BK * SST];

    const int tid  = threadIdx.x;
    const int lane = tid & 31;
    const int warp = tid >> 5;
    const int wm   = warp >> 2;   // 0..1
    const int wn   = warp & 3;    // 0..3
    const int g    = lane >> 2;   // 0..7
    const int q    = lane & 3;    // 0..3

    const int row0 = blockIdx.y * BM;
    const int col0 = blockIdx.x * BN;

    // gmem->smem mapping: lkq = k-quad (0..7), lm + 32p = row within tile
    const int lkq = tid >> 5;
    const int lm  = tid & 31;

    int aoffs[4], woffs[4];
#pragma unroll
    for (int p = 0; p < 4; p++) {
        int r = row0 + lm + 32*p;
        aoffs[p] = a_off ? a_off[r] : r * K;
        woffs[p] = (col0 + lm + 32*p) * K;
    }

    float acc[4][4][4];
#pragma unroll
    for (int a = 0; a < 4; a++)
#pragma unroll
        for (int b = 0; b < 4; b++)
#pragma unroll
            for (int c = 0; c < 4; c++) acc[a][b][c] = 0.f;

    const int KT = K / BK;

    for (int kt = 0; kt < KT; kt++) {
        int kbase = kt*BK + lkq*4;
#pragma unroll
        for (int p = 0; p < 4; p++) {
            float4 va = *(const float4*)(A + aoffs[p] + kbase);
            float4 vw = *(const float4*)(W + woffs[p] + kbase);
            int m = lm + 32*p;
            const float* pa = (const float*)&va;
            const float* pw = (const float*)&vw;
#pragma unroll
            for (int e = 0; e < 4; e++) {
                unsigned int ta, tw;
                asm("cvt.rna.tf32.f32 %0, %1;" : "=r"(ta) : "f"(pa[e]));
                asm("cvt.rna.tf32.f32 %0, %1;" : "=r"(tw) : "f"(pw[e]));
                As[(lkq*4 + e) * SST + m] = ta;
                Ws[(lkq*4 + e) * SST + m] = tw;
            }
        }
        __syncthreads();

#pragma unroll
        for (int kk = 0; kk < 4; kk++) {
            unsigned int af[4][4];
            unsigned int wf[4][2];
#pragma unroll
            for (int mi = 0; mi < 4; mi++) {
                int mrow = wm*64 + mi*16;
                af[mi][0] = As[(kk*8 + q    ) * SST + mrow + g    ];
                af[mi][1] = As[(kk*8 + q    ) * SST + mrow + g + 8];
                af[mi][2] = As[(kk*8 + q + 4) * SST + mrow + g    ];
                af[mi][3] = As[(kk*8 + q + 4) * SST + mrow + g + 8];
            }
#pragma unroll
            for (int ni = 0; ni < 4; ni++) {
                int ncol = wn*32 + ni*8;
                wf[ni][0] = Ws[(kk*8 + q    ) * SST + ncol + g];
                wf[ni][1] = Ws[(kk*8 + q + 4) * SST + ncol + g];
            }
#pragma unroll
            for (int mi = 0; mi < 4; mi++)
#pragma unroll
                for (int ni = 0; ni < 4; ni++)
                    asm volatile(
                        "mma.sync.aligned.m16n8k8.row.col.f32.tf32.tf32.f32 "
                        "{%0,%1,%2,%3}, {%4,%5,%6,%7}, {%8,%9}, {%0,%1,%2,%3};"
                        : "+f"(acc[mi][ni][0]), "+f"(acc[mi][ni][1]),
                          "+f"(acc[mi][ni][2]), "+f"(acc[mi][ni][3])
                        : "r"(af[mi][0]), "r"(af[mi][1]), "r"(af[mi][2]), "r"(af[mi][3]),
                          "r"(wf[ni][0]), "r"(wf[ni][1]));
        }
        __syncthreads();
    }

    // epilogue
#pragma unroll
    for (int mi = 0; mi < 4; mi++) {
        int r0 = row0 + wm*64 + mi*16 + g;
#pragma unroll
        for (int ni = 0; ni < 4; ni++) {
            int c = col0 + wn*32 + ni*8 + 2*q;
            float b0 = 0.f, b1 = 0.f;
            if (bias) { b0 = bias[c]; b1 = bias[c+1]; }
            float2 v0 = make_float2(acc[mi][ni][0] + b0, acc[mi][ni][1] + b1);
            float2 v1 = make_float2(acc[mi][ni][2] + b0, acc[mi][ni][3] + b1);
            *(float2*)(C + (size_t)r0      * N + c) = v0;
            *(float2*)(C + (size_t)(r0+8)  * N + c) = v1;
        }
    }
}

// ---------------- GRU pointwise updates ----------------
__global__ void k_pw0(const float* __restrict__ bih, const float* __restrict__ bhh, int t) {
    if (t >= d_T[0]) return;
    int i = blockIdx.x * blockDim.x + threadIdx.x;
    if (i >= BSZ*HSZ) return;
    int b = i >> 9, j = i & (HSZ-1);
    int base = b*H3 + j;
    float xr = d_A0[base        ] + bih[j        ];
    float xz = d_A0[base +   HSZ] + bih[j +   HSZ];
    float xn = d_A0[base + 2*HSZ] + bih[j + 2*HSZ];
    float gr = d_G0[base        ] + bhh[j        ];
    float gz = d_G0[base +   HSZ] + bhh[j +   HSZ];
    float gn = d_G0[base + 2*HSZ] + bhh[j + 2*HSZ];
    float r = 1.f / (1.f + expf(-(xr + gr)));
    float z = 1.f / (1.f + expf(-(xz + gz)));
    float n = tanhf(xn + r * gn);
    d_h0[i] = (1.f - z) * n + z * d_h0[i];
}

__global__ void k_pw1(const float* __restrict__ bih, const float* __restrict__ bhh, int t) {
    if (t >= d_T[0]) return;
    int i = blockIdx.x * blockDim.x + threadIdx.x;
    if (i >= BSZ*HSZ) return;
    int b = i >> 9, j = i & (HSZ-1);
    int base = b*H3 + j;
    float xr = d_A1[base        ] + bih[j        ];
    float xz = d_A1[base +   HSZ] + bih[j +   HSZ];
    float xn = d_A1[base + 2*HSZ] + bih[j + 2*HSZ];
    float gr = d_G1b[base        ] + bhh[j        ];
    float gz = d_G1b[base +   HSZ] + bhh[j +   HSZ];
    float gn = d_G1b[base + 2*HSZ] + bhh[j + 2*HSZ];
    float r = 1.f / (1.f + expf(-(xr + gr)));
    float z = 1.f / (1.f + expf(-(xz + gz)));
    float n = tanhf(xn + r * gn);
    float hnew = (1.f - z) * n + z * d_h1[i];
    d_h1[i] = hnew;
    d_Y1[(size_t)t * (BSZ*HSZ) + i] = hnew;
}

// ---------------- host launch ----------------
static void launch_gemm(const float* A, const float* W, float* C,
                        int M, int N, int K, const int* aoff, const float* bias,
                        int t, int chk)
{
    dim3 grid(N / BN, M / BM);
    gemm_tf32<<<grid, 256>>>(A, W, C, M, N, K, aoff, bias, t, chk);
}

extern "C" void kernel_launch(void* const* d_in, const int* in_sizes, int n_in,
                              void* d_out, int out_size)
{
    const float* x    = (const float*)d_in[0];
    const float* Wih0 = (const float*)d_in[1];
    const float* Whh0 = (const float*)d_in[2];
    const float* bih0 = (const float*)d_in[3];
    const float* bhh0 = (const float*)d_in[4];
    const float* Wih1 = (const float*)d_in[5];
    const float* Whh1 = (const float*)d_in[6];
    const float* bih1 = (const float*)d_in[7];
    const float* bhh1 = (const float*)d_in[8];
    const float* Wout = (const float*)d_in[9];
    const float* bout = (const float*)d_in[10];
    const int*   psi  = (const int*)d_in[11];
    float* out = (float*)d_out;

    float *p_h0, *p_h1, *p_A0, *p_G0, *p_G1b, *p_A1, *p_Y1;
    int *p_rowoff;
    cudaGetSymbolAddress((void**)&p_h0,  d_h0);
    cudaGetSymbolAddress((void**)&p_h1,  d_h1);
    cudaGetSymbolAddress((void**)&p_A0,  d_A0);
    cudaGetSymbolAddress((void**)&p_G0,  d_G0);
    cudaGetSymbolAddress((void**)&p_G1b, d_G1b);
    cudaGetSymbolAddress((void**)&p_A1,  d_A1);
    cudaGetSymbolAddress((void**)&p_Y1,  d_Y1);
    cudaGetSymbolAddress((void**)&p_rowoff, d_rowoff);

    const int PWG = (BSZ*HSZ + 255) / 256;

    k_init <<<PWG, 256>>>();
    k_first<<<(NSZ + 255) / 256, 256>>>(psi);
    k_rank <<<(NSZ + 255) / 256, 256>>>(psi);

    // layer-0 input projection, computed once (timestep input is constant)
    launch_gemm(x, Wih0, p_A0, BSZ, H3, INSZ, nullptr, nullptr, 0, 0);

    for (int t = 0; t < T_MAX; t++) {
        // recurrent projections from state at t-1 (independent)
        launch_gemm(p_h0, Whh0, p_G0,  BSZ, H3, HSZ, nullptr, nullptr, t, 1);
        launch_gemm(p_h1, Whh1, p_G1b, BSZ, H3, HSZ, nullptr, nullptr, t, 1);
        // layer-0 state update -> h0_t
        k_pw0<<<PWG, 256>>>(bih0, bhh0, t);
        // layer-1 input projection from h0_t
        launch_gemm(p_h0, Wih1, p_A1, BSZ, H3, HSZ, nullptr, nullptr, t, 1);
        // layer-1 state update -> h1_t, store into Y1[t]
        k_pw1<<<PWG, 256>>>(bih1, bhh1, t);
    }

    // gathered output GEMM: out[N, OUT] = Y1[rowoff[j]] . Wout^T + bout
    launch_gemm(p_Y1, Wout, out, NSZ, OUTSZ, HSZ, p_rowoff, bout, 0, 0);
    (void)in_sizes; (void)n_in; (void)out_size;
}

// round 3
// speedup vs baseline: 1.8351x; 1.8351x over previous
#include <cuda_runtime.h>
#include <math.h>
#include <stdint.h>

// Problem constants
#define BSZ   2048
#define INSZ  512
#define HSZ   512
#define OUTSZ 256
#define NSZ   32768
#define H3    (3*HSZ)
#define T_MAX 48

#define BM 128
#define BN 128
#define BK 32
#define STAGES 3
#define STAGE_FLOATS (2*BM*BK)            // A tile + W tile = 8192 floats
#define SMEM_BYTES   (STAGES*STAGE_FLOATS*4)  // 98304 B

// ---------------- device scratch (static, no allocations) ----------------
__device__ float d_h0 [BSZ*HSZ];
__device__ float d_h1 [BSZ*HSZ];
__device__ float d_h0r[BSZ*HSZ];
__device__ float d_h1r[BSZ*HSZ];
__device__ float d_A0 [BSZ*H3];
__device__ float d_G0 [BSZ*H3];
__device__ float d_G1 [BSZ*H3];
__device__ float d_A1 [BSZ*H3];
__device__ float d_Y1r[(size_t)T_MAX*BSZ*HSZ];
__device__ float d_xr   [BSZ*INSZ];
__device__ float d_Wih0r[H3*INSZ];
__device__ float d_Whh0r[H3*HSZ];
__device__ float d_Wih1r[H3*HSZ];
__device__ float d_Whh1r[H3*HSZ];
__device__ float d_Woutr[OUTSZ*HSZ];
__device__ int   d_first[BSZ];
__device__ int   d_rowoff[NSZ];
__device__ int   d_T[1];

__device__ __forceinline__ float tf32r(float x) {
    unsigned u;
    asm("cvt.rna.tf32.f32 %0, %1;" : "=r"(u) : "f"(x));
    return __uint_as_float(u);
}

// ---------------- setup kernels ----------------
__global__ void k_init() {
    int i = blockIdx.x * blockDim.x + threadIdx.x;
    if (i == 0) d_T[0] = 0;
    if (i < BSZ*HSZ) { d_h0[i]=0.f; d_h1[i]=0.f; d_h0r[i]=0.f; d_h1r[i]=0.f; }
}

__global__ void k_round(const float* __restrict__ src, float* __restrict__ dst, int n) {
    int i = blockIdx.x * blockDim.x + threadIdx.x;
    if (i < n) dst[i] = tf32r(src[i]);
}

__global__ void k_first(const int* __restrict__ psi) {
    int j = blockIdx.x * blockDim.x + threadIdx.x;
    if (j >= NSZ) return;
    if (j == 0 || psi[j] != psi[j-1]) d_first[psi[j]] = j;
}

__global__ void k_rank(const int* __restrict__ psi) {
    int j = blockIdx.x * blockDim.x + threadIdx.x;
    if (j >= NSZ) return;
    int v = psi[j];
    int r = j - d_first[v];
    d_rowoff[j] = r * (BSZ*HSZ) + v * HSZ;
    atomicMax(&d_T[0], r + 1);
}

// ---------------- TF32 mma GEMM with cp.async 3-stage pipeline ----------------
// C[M,N] = A[M,K] * W[N,K]^T (+bias). A rows optionally gathered via a_off.
// blockIdx.z selects operand set (Aa/Wa/Ca vs Ab/Wb/Cb) so two independent
// GEMMs share one launch.
__global__ __launch_bounds__(256, 2)
void gemm_tf32(const float* __restrict__ Aa, const float* __restrict__ Wa, float* __restrict__ Ca,
               const float* __restrict__ Ab, const float* __restrict__ Wb, float* __restrict__ Cb,
               int M, int N, int K,
               const int* __restrict__ a_off, const float* __restrict__ bias,
               int t_step, int check_T)
{
    if (check_T && t_step >= d_T[0]) return;

    const float* A = blockIdx.z ? Ab : Aa;
    const float* W = blockIdx.z ? Wb : Wa;
    float*       C = blockIdx.z ? Cb : Ca;

    extern __shared__ float sm[];
    const uint32_t smaddr = (uint32_t)__cvta_generic_to_shared(sm);

    const int tid  = threadIdx.x;
    const int lane = tid & 31;
    const int warp = tid >> 5;
    const int wm   = warp >> 2;
    const int wn   = warp & 3;
    const int g    = lane >> 2;
    const int q    = lane & 3;

    const int row0 = blockIdx.y * BM;
    const int col0 = blockIdx.x * BN;

    // ---- loader mapping: thread t loads row lm, 16B-groups lkg0..lkg0+3 ----
    const int lm   = tid >> 1;        // 0..127
    const int lkg0 = (tid & 1) * 4;   // 0 or 4

    int arow = a_off ? a_off[row0 + lm] : (row0 + lm) * K;
    const float* agp = A + arow + lkg0*4;
    const float* wgp = W + (col0 + lm) * K + lkg0*4;

    int soff[4];
#pragma unroll
    for (int j = 0; j < 4; j++)
        soff[j] = lm*BK + (((lkg0 + j) ^ (lm & 7)) << 2);   // xor-swizzled dst (floats)

#define LOAD_STAGE(st, kt) do {                                              \
        uint32_t dA = smaddr + (st)*STAGE_FLOATS*4;                          \
        uint32_t dW = dA + BM*BK*4;                                          \
        const float* ga = agp + (kt)*BK;                                     \
        const float* gw = wgp + (kt)*BK;                                     \
        _Pragma("unroll")                                                    \
        for (int j = 0; j < 4; j++) {                                        \
            asm volatile("cp.async.cg.shared.global [%0], [%1], 16;"         \
                         :: "r"(dA + soff[j]*4), "l"(ga + j*4));             \
            asm volatile("cp.async.cg.shared.global [%0], [%1], 16;"         \
                         :: "r"(dW + soff[j]*4), "l"(gw + j*4));             \
        }                                                                    \
    } while (0)

    float acc[4][4][4];
#pragma unroll
    for (int a = 0; a < 4; a++)
#pragma unroll
        for (int b = 0; b < 4; b++)
#pragma unroll
            for (int c = 0; c < 4; c++) acc[a][b][c] = 0.f;

    const int KT = K / BK;

    // prologue: fill STAGES-1 stages
#pragma unroll
    for (int s = 0; s < STAGES-1; s++) {
        LOAD_STAGE(s, s);
        asm volatile("cp.async.commit_group;" ::: "memory");
    }

    const int abase  = (wm*64 + g)*BK + q;   // A fragment base (floats)
    const int nbase  = (wn*32 + g)*BK + q;   // W fragment base (floats)

    for (int kt = 0; kt < KT; kt++) {
        asm volatile("cp.async.wait_group %0;" :: "n"(STAGES-2) : "memory");
        __syncthreads();

        int ktn = kt + STAGES - 1;
        if (ktn < KT) LOAD_STAGE(ktn % STAGES, ktn);
        asm volatile("cp.async.commit_group;" ::: "memory");

        const int st = kt % STAGES;
        const uint32_t* sA = (const uint32_t*)sm + st*STAGE_FLOATS;
        const uint32_t* sW = sA + BM*BK;

#pragma unroll
        for (int kk = 0; kk < 4; kk++) {
            const int e0 = (((2*kk)     ^ g) << 2);
            const int e1 = (((2*kk + 1) ^ g) << 2);
            uint32_t af[4][4];
            uint32_t wf[4][2];
#pragma unroll
            for (int mi = 0; mi < 4; mi++) {
                int b = abase + mi*16*BK;
                af[mi][0] = sA[b + e0];
                af[mi][1] = sA[b + 8*BK + e0];
                af[mi][2] = sA[b + e1];
                af[mi][3] = sA[b + 8*BK + e1];
            }
#pragma unroll
            for (int ni = 0; ni < 4; ni++) {
                int b = nbase + ni*8*BK;
                wf[ni][0] = sW[b + e0];
                wf[ni][1] = sW[b + e1];
            }
#pragma unroll
            for (int mi = 0; mi < 4; mi++)
#pragma unroll
                for (int ni = 0; ni < 4; ni++)
                    asm volatile(
                        "mma.sync.aligned.m16n8k8.row.col.f32.tf32.tf32.f32 "
                        "{%0,%1,%2,%3}, {%4,%5,%6,%7}, {%8,%9}, {%0,%1,%2,%3};"
                        : "+f"(acc[mi][ni][0]), "+f"(acc[mi][ni][1]),
                          "+f"(acc[mi][ni][2]), "+f"(acc[mi][ni][3])
                        : "r"(af[mi][0]), "r"(af[mi][1]), "r"(af[mi][2]), "r"(af[mi][3]),
                          "r"(wf[ni][0]), "r"(wf[ni][1]));
        }
    }

    // epilogue
#pragma unroll
    for (int mi = 0; mi < 4; mi++) {
        int r0 = row0 + wm*64 + mi*16 + g;
#pragma unroll
        for (int ni = 0; ni < 4; ni++) {
            int c = col0 + wn*32 + ni*8 + 2*q;
            float b0 = 0.f, b1 = 0.f;
            if (bias) { b0 = bias[c]; b1 = bias[c+1]; }
            float2 v0 = make_float2(acc[mi][ni][0] + b0, acc[mi][ni][1] + b1);
            float2 v1 = make_float2(acc[mi][ni][2] + b0, acc[mi][ni][3] + b1);
            *(float2*)(C + (size_t)r0     * N + c) = v0;
            *(float2*)(C + (size_t)(r0+8) * N + c) = v1;
        }
    }
#undef LOAD_STAGE
}

// ---------------- GRU pointwise updates (float4 vectorized) ----------------
__device__ __forceinline__ void gru_elem(float xr, float xz, float xn,
                                         float gr, float gz, float gn,
                                         float h, float& hn_out)
{
    float r = 1.f / (1.f + expf(-(xr + gr)));
    float z = 1.f / (1.f + expf(-(xz + gz)));
    float n = tanhf(xn + r * gn);
    hn_out = (1.f - z) * n + z * h;
}

__global__ void k_pw0(const float* __restrict__ bih, const float* __restrict__ bhh, int t) {
    if (t >= d_T[0]) return;
    int i4 = blockIdx.x * blockDim.x + threadIdx.x;
    if (i4 >= BSZ*HSZ/4) return;
    int i = i4 << 2;
    int b = i >> 9, j = i & (HSZ-1);
    int base = b*H3 + j;
    float4 ar = *(const float4*)(d_A0 + base);
    float4 az = *(const float4*)(d_A0 + base + HSZ);
    float4 an = *(const float4*)(d_A0 + base + 2*HSZ);
    float4 gr = *(const float4*)(d_G0 + base);
    float4 gz = *(const float4*)(d_G0 + base + HSZ);
    float4 gn = *(const float4*)(d_G0 + base + 2*HSZ);
    float4 h  = *(const float4*)(d_h0 + i);
    float4 bir = *(const float4*)(bih + j);
    float4 biz = *(const float4*)(bih + j + HSZ);
    float4 bin = *(const float4*)(bih + j + 2*HSZ);
    float4 bhr = *(const float4*)(bhh + j);
    float4 bhz = *(const float4*)(bhh + j + HSZ);
    float4 bhn = *(const float4*)(bhh + j + 2*HSZ);

    float hn[4];
    const float* pxr=(const float*)&ar; const float* pxz=(const float*)&az; const float* pxn=(const float*)&an;
    const float* pgr=(const float*)&gr; const float* pgz=(const float*)&gz; const float* pgn=(const float*)&gn;
    const float* ph =(const float*)&h;
    const float* pir=(const float*)&bir; const float* piz=(const float*)&biz; const float* pin=(const float*)&bin;
    const float* phr=(const float*)&bhr; const float* phz=(const float*)&bhz; const float* phn=(const float*)&bhn;
#pragma unroll
    for (int e = 0; e < 4; e++)
        gru_elem(pxr[e]+pir[e], pxz[e]+piz[e], pxn[e]+pin[e],
                 pgr[e]+phr[e], pgz[e]+phz[e], pgn[e]+phn[e], ph[e], hn[e]);

    float4 hv = make_float4(hn[0], hn[1], hn[2], hn[3]);
    float4 hr = make_float4(tf32r(hn[0]), tf32r(hn[1]), tf32r(hn[2]), tf32r(hn[3]));
    *(float4*)(d_h0  + i) = hv;
    *(float4*)(d_h0r + i) = hr;
}

__global__ void k_pw1(const float* __restrict__ bih, const float* __restrict__ bhh, int t) {
    if (t >= d_T[0]) return;
    int i4 = blockIdx.x * blockDim.x + threadIdx.x;
    if (i4 >= BSZ*HSZ/4) return;
    int i = i4 << 2;
    int b = i >> 9, j = i & (HSZ-1);
    int base = b*H3 + j;
    float4 ar = *(const float4*)(d_A1 + base);
    float4 az = *(const float4*)(d_A1 + base + HSZ);
    float4 an = *(const float4*)(d_A1 + base + 2*HSZ);
    float4 gr = *(const float4*)(d_G1 + base);
    float4 gz = *(const float4*)(d_G1 + base + HSZ);
    float4 gn = *(const float4*)(d_G1 + base + 2*HSZ);
    float4 h  = *(const float4*)(d_h1 + i);
    float4 bir = *(const float4*)(bih + j);
    float4 biz = *(const float4*)(bih + j + HSZ);
    float4 bin = *(const float4*)(bih + j + 2*HSZ);
    float4 bhr = *(const float4*)(bhh + j);
    float4 bhz = *(const float4*)(bhh + j + HSZ);
    float4 bhn = *(const float4*)(bhh + j + 2*HSZ);

    float hn[4];
    const float* pxr=(const float*)&ar; const float* pxz=(const float*)&az; const float* pxn=(const float*)&an;
    const float* pgr=(const float*)&gr; const float* pgz=(const float*)&gz; const float* pgn=(const float*)&gn;
    const float* ph =(const float*)&h;
    const float* pir=(const float*)&bir; const float* piz=(const float*)&biz; const float* pin=(const float*)&bin;
    const float* phr=(const float*)&bhr; const float* phz=(const float*)&bhz; const float* phn=(const float*)&bhn;
#pragma unroll
    for (int e = 0; e < 4; e++)
        gru_elem(pxr[e]+pir[e], pxz[e]+piz[e], pxn[e]+pin[e],
                 pgr[e]+phr[e], pgz[e]+phz[e], pgn[e]+phn[e], ph[e], hn[e]);

    float4 hv = make_float4(hn[0], hn[1], hn[2], hn[3]);
    float4 hr = make_float4(tf32r(hn[0]), tf32r(hn[1]), tf32r(hn[2]), tf32r(hn[3]));
    *(float4*)(d_h1  + i) = hv;
    *(float4*)(d_h1r + i) = hr;
    *(float4*)(d_Y1r + (size_t)t * (BSZ*HSZ) + i) = hr;
}

// ---------------- host launch ----------------
static void launch_gemm1(const float* A, const float* W, float* C,
                         int M, int N, int K, const int* aoff, const float* bias,
                         int t, int chk)
{
    dim3 grid(N / BN, M / BM, 1);
    gemm_tf32<<<grid, 256, SMEM_BYTES>>>(A, W, C, A, W, C, M, N, K, aoff, bias, t, chk);
}

extern "C" void kernel_launch(void* const* d_in, const int* in_sizes, int n_in,
                              void* d_out, int out_size)
{
    const float* x    = (const float*)d_in[0];
    const float* Wih0 = (const float*)d_in[1];
    const float* Whh0 = (const float*)d_in[2];
    const float* bih0 = (const float*)d_in[3];
    const float* bhh0 = (const float*)d_in[4];
    const float* Wih1 = (const float*)d_in[5];
    const float* Whh1 = (const float*)d_in[6];
    const float* bih1 = (const float*)d_in[7];
    const float* bhh1 = (const float*)d_in[8];
    const float* Wout = (const float*)d_in[9];
    const float* bout = (const float*)d_in[10];
    const int*   psi  = (const int*)d_in[11];
    float* out = (float*)d_out;

    cudaFuncSetAttribute(gemm_tf32, cudaFuncAttributeMaxDynamicSharedMemorySize, SMEM_BYTES);

    float *p_h0r, *p_h1r, *p_A0, *p_G0, *p_G1, *p_A1, *p_Y1r;
    float *p_xr, *p_Wih0r, *p_Whh0r, *p_Wih1r, *p_Whh1r, *p_Woutr;
    int *p_rowoff;
    cudaGetSymbolAddress((void**)&p_h0r,   d_h0r);
    cudaGetSymbolAddress((void**)&p_h1r,   d_h1r);
    cudaGetSymbolAddress((void**)&p_A0,    d_A0);
    cudaGetSymbolAddress((void**)&p_G0,    d_G0);
    cudaGetSymbolAddress((void**)&p_G1,    d_G1);
    cudaGetSymbolAddress((void**)&p_A1,    d_A1);
    cudaGetSymbolAddress((void**)&p_Y1r,   d_Y1r);
    cudaGetSymbolAddress((void**)&p_xr,    d_xr);
    cudaGetSymbolAddress((void**)&p_Wih0r, d_Wih0r);
    cudaGetSymbolAddress((void**)&p_Whh0r, d_Whh0r);
    cudaGetSymbolAddress((void**)&p_Wih1r, d_Wih1r);
    cudaGetSymbolAddress((void**)&p_Whh1r, d_Whh1r);
    cudaGetSymbolAddress((void**)&p_Woutr, d_Woutr);
    cudaGetSymbolAddress((void**)&p_rowoff, d_rowoff);

    const int PW4 = (BSZ*HSZ/4 + 255) / 256;
    const int PWI = (BSZ*HSZ + 255) / 256;

    k_init <<<PWI, 256>>>();
    k_first<<<(NSZ + 255) / 256, 256>>>(psi);
    k_rank <<<(NSZ + 255) / 256, 256>>>(psi);

    // pre-round weights and x to tf32 (RNA), once per launch
    k_round<<<(BSZ*INSZ  + 255)/256, 256>>>(x,    p_xr,    BSZ*INSZ);
    k_round<<<(H3*INSZ   + 255)/256, 256>>>(Wih0, p_Wih0r, H3*INSZ);
    k_round<<<(H3*HSZ    + 255)/256, 256>>>(Whh0, p_Whh0r, H3*HSZ);
    k_round<<<(H3*HSZ    + 255)/256, 256>>>(Wih1, p_Wih1r, H3*HSZ);
    k_round<<<(H3*HSZ    + 255)/256, 256>>>(Whh1, p_Whh1r, H3*HSZ);
    k_round<<<(OUTSZ*HSZ + 255)/256, 256>>>(Wout, p_Woutr, OUTSZ*HSZ);

    // layer-0 input projection, computed once (timestep input is constant)
    launch_gemm1(p_xr, p_Wih0r, p_A0, BSZ, H3, INSZ, nullptr, nullptr, 0, 0);

    for (int t = 0; t < T_MAX; t++) {
        // two independent recurrent projections in ONE launch (gridDim.z = 2)
        {
            dim3 grid(H3 / BN, BSZ / BM, 2);
            gemm_tf32<<<grid, 256, SMEM_BYTES>>>(
                p_h0r, p_Whh0r, p_G0,
                p_h1r, p_Whh1r, p_G1,
                BSZ, H3, HSZ, nullptr, nullptr, t, 1);
        }
        k_pw0<<<PW4, 256>>>(bih0, bhh0, t);
        launch_gemm1(p_h0r, p_Wih1r, p_A1, BSZ, H3, HSZ, nullptr, nullptr, t, 1);
        k_pw1<<<PW4, 256>>>(bih1, bhh1, t);
    }

    // gathered output GEMM: out[N, OUT] = Y1r[rowoff[j]] . Wout^T + bout
    launch_gemm1(p_Y1r, p_Woutr, out, NSZ, OUTSZ, HSZ, p_rowoff, bout, 0, 0);

    (void)in_sizes; (void)n_in; (void)out_size;
}

// round 5
// speedup vs baseline: 3.0058x; 1.6380x over previous
#include <cuda_runtime.h>
#include <cuda_fp16.h>
#include <math.h>
#include <stdint.h>

// Problem constants
#define BSZ   2048
#define INSZ  512
#define HSZ   512
#define OUTSZ 256
#define NSZ   32768
#define H3    (3*HSZ)
#define T_MAX 48

#define BM 128
#define BN 128
#define BKH 64                              // k per smem tile (halfs) = 128B rows
#define ROWU32 32                           // u32 words per smem row (128B)
#define STAGE_U32 (2*BM*ROWU32)             // A tile + W tile = 8192 u32 = 32KB
#define STAGES 3
#define SMEM_BYTES (STAGES*STAGE_U32*4)     // 98304 B

// ---------------- device scratch (static, no allocations) ----------------
__device__ float  d_h0 [BSZ*HSZ];
__device__ float  d_h1 [BSZ*HSZ];
__device__ __half d_h0h[BSZ*HSZ];
__device__ __half d_h1h[BSZ*HSZ];
__device__ float  d_A0 [BSZ*H3];
__device__ float  d_G0 [BSZ*H3];
__device__ float  d_G1 [BSZ*H3];
__device__ float  d_A1 [BSZ*H3];
__device__ __half d_Y1h[(size_t)T_MAX*BSZ*HSZ];
__device__ __half d_xh   [BSZ*INSZ];
__device__ __half d_Wih0h[H3*INSZ];
__device__ __half d_Whh0h[H3*HSZ];
__device__ __half d_Wih1h[H3*HSZ];
__device__ __half d_Whh1h[H3*HSZ];
__device__ __half d_Wouth[OUTSZ*HSZ];
__device__ int    d_first[BSZ];
__device__ int    d_rowoff[NSZ];
__device__ int    d_T[1];

// ---------------- setup kernels ----------------
__global__ void k_init() {
    int i = blockIdx.x * blockDim.x + threadIdx.x;
    if (i == 0) d_T[0] = 0;
    if (i < BSZ*HSZ) {
        d_h0[i]=0.f; d_h1[i]=0.f;
        d_h0h[i]=__float2half(0.f); d_h1h[i]=__float2half(0.f);
    }
}

__global__ void k_tohalf(const float* __restrict__ src, __half* __restrict__ dst, int n4) {
    int i4 = blockIdx.x * blockDim.x + threadIdx.x;
    if (i4 >= n4) return;
    int i = i4 << 2;
    float4 v = *(const float4*)(src + i);
    __half2 p0 = __floats2half2_rn(v.x, v.y);
    __half2 p1 = __floats2half2_rn(v.z, v.w);
    ((__half2*)(dst + i))[0] = p0;
    ((__half2*)(dst + i))[1] = p1;
}

__global__ void k_first(const int* __restrict__ psi) {
    int j = blockIdx.x * blockDim.x + threadIdx.x;
    if (j >= NSZ) return;
    if (j == 0 || psi[j] != psi[j-1]) d_first[psi[j]] = j;
}

__global__ void k_rank(const int* __restrict__ psi) {
    int j = blockIdx.x * blockDim.x + threadIdx.x;
    if (j >= NSZ) return;
    int v = psi[j];
    int r = j - d_first[v];
    d_rowoff[j] = r * (BSZ*HSZ) + v * HSZ;   // element offset of row start
    atomicMax(&d_T[0], r + 1);
}

// ---------------- fp16 mma GEMM with cp.async 3-stage pipeline ----------------
// C[M,N] = A[M,K] * W[N,K]^T (+bias), A/W fp16, accum fp32.
// A rows optionally gathered via a_off. blockIdx.z picks operand set.
__global__ __launch_bounds__(256, 2)
void gemm_fp16(const __half* __restrict__ Aa, const __half* __restrict__ Wa, float* __restrict__ Ca,
               const __half* __restrict__ Ab, const __half* __restrict__ Wb, float* __restrict__ Cb,
               int M, int N, int K,
               const int* __restrict__ a_off, const float* __restrict__ bias,
               int t_step, int check_T)
{
    if (check_T && t_step >= d_T[0]) return;

    const __half* A = blockIdx.z ? Ab : Aa;
    const __half* W = blockIdx.z ? Wb : Wa;
    float*        C = blockIdx.z ? Cb : Ca;

    extern __shared__ uint32_t sm[];
    const uint32_t smaddr = (uint32_t)__cvta_generic_to_shared(sm);

    const int tid  = threadIdx.x;
    const int lane = tid & 31;
    const int warp = tid >> 5;
    const int wm   = warp >> 2;   // 0..1
    const int wn   = warp & 3;    // 0..3
    const int g    = lane >> 2;   // 0..7
    const int q    = lane & 3;    // 0..3

    const int row0 = blockIdx.y * BM;
    const int col0 = blockIdx.x * BN;

    // ---- loader mapping: thread t loads row t>>1, 16B-groups (t&1)*4 .. +3 ----
    const int lm   = tid >> 1;        // 0..127
    const int lkg0 = (tid & 1) * 4;   // 0 or 4

    long arow = a_off ? (long)a_off[row0 + lm] : (long)(row0 + lm) * K;
    const __half* agp = A + arow;
    const __half* wgp = W + (long)(col0 + lm) * K;

    uint32_t soffB[4];
#pragma unroll
    for (int j = 0; j < 4; j++)
        soffB[j] = (uint32_t)(lm * 128 + (((lkg0 + j) ^ (lm & 7)) << 4));  // bytes

#define LOAD_STAGE(st, kt) do {                                              \
        uint32_t dA = smaddr + (st)*STAGE_U32*4;                             \
        uint32_t dW = dA + BM*ROWU32*4;                                      \
        const __half* ga = agp + (size_t)(kt)*BKH;                           \
        const __half* gw = wgp + (size_t)(kt)*BKH;                           \
        _Pragma("unroll")                                                    \
        for (int j = 0; j < 4; j++) {                                        \
            asm volatile("cp.async.cg.shared.global [%0], [%1], 16;"         \
                         :: "r"(dA + soffB[j]), "l"(ga + (lkg0 + j)*8));     \
            asm volatile("cp.async.cg.shared.global [%0], [%1], 16;"         \
                         :: "r"(dW + soffB[j]), "l"(gw + (lkg0 + j)*8));     \
        }                                                                    \
    } while (0)

    float acc[4][4][4];
#pragma unroll
    for (int a = 0; a < 4; a++)
#pragma unroll
        for (int b = 0; b < 4; b++)
#pragma unroll
            for (int c = 0; c < 4; c++) acc[a][b][c] = 0.f;

    const int KT = K / BKH;   // 8 for K=512

    // prologue: fill STAGES-1 stages
#pragma unroll
    for (int s = 0; s < STAGES-1; s++) {
        LOAD_STAGE(s, s);
        asm volatile("cp.async.commit_group;" ::: "memory");
    }

    const int abase = (wm*64 + g)*ROWU32 + q;   // A fragment base (u32 index)
    const int nbase = (wn*32 + g)*ROWU32 + q;   // W fragment base

    for (int kt = 0; kt < KT; kt++) {
        asm volatile("cp.async.wait_group %0;" :: "n"(STAGES-2) : "memory");
        __syncthreads();

        int ktn = kt + STAGES - 1;
        if (ktn < KT) LOAD_STAGE(ktn % STAGES, ktn);
        asm volatile("cp.async.commit_group;" ::: "memory");

        const int st = kt % STAGES;
        const uint32_t* sA = sm + st*STAGE_U32;
        const uint32_t* sW = sA + BM*ROWU32;

#pragma unroll
        for (int kk = 0; kk < 4; kk++) {     // 4 x k16 per 64-half tile
            const int e0 = (((2*kk)     ^ g) << 2);
            const int e1 = (((2*kk + 1) ^ g) << 2);
            uint32_t af[4][4];
            uint32_t wf[4][2];
#pragma unroll
            for (int mi = 0; mi < 4; mi++) {
                int b = abase + mi*16*ROWU32;
                af[mi][0] = sA[b + e0];               // row g,   k lo
                af[mi][1] = sA[b + 8*ROWU32 + e0];    // row g+8, k lo
                af[mi][2] = sA[b + e1];               // row g,   k hi
                af[mi][3] = sA[b + 8*ROWU32 + e1];    // row g+8, k hi
            }
#pragma unroll
            for (int ni = 0; ni < 4; ni++) {
                int b = nbase + ni*8*ROWU32;
                wf[ni][0] = sW[b + e0];
                wf[ni][1] = sW[b + e1];
            }
#pragma unroll
            for (int mi = 0; mi < 4; mi++)
#pragma unroll
                for (int ni = 0; ni < 4; ni++)
                    asm volatile(
                        "mma.sync.aligned.m16n8k16.row.col.f32.f16.f16.f32 "
                        "{%0,%1,%2,%3}, {%4,%5,%6,%7}, {%8,%9}, {%0,%1,%2,%3};"
                        : "+f"(acc[mi][ni][0]), "+f"(acc[mi][ni][1]),
                          "+f"(acc[mi][ni][2]), "+f"(acc[mi][ni][3])
                        : "r"(af[mi][0]), "r"(af[mi][1]), "r"(af[mi][2]), "r"(af[mi][3]),
                          "r"(wf[ni][0]), "r"(wf[ni][1]));
        }
    }

    // epilogue
#pragma unroll
    for (int mi = 0; mi < 4; mi++) {
        int r0 = row0 + wm*64 + mi*16 + g;
#pragma unroll
        for (int ni = 0; ni < 4; ni++) {
            int c = col0 + wn*32 + ni*8 + 2*q;
            float b0 = 0.f, b1 = 0.f;
            if (bias) { b0 = bias[c]; b1 = bias[c+1]; }
            float2 v0 = make_float2(acc[mi][ni][0] + b0, acc[mi][ni][1] + b1);
            float2 v1 = make_float2(acc[mi][ni][2] + b0, acc[mi][ni][3] + b1);
            *(float2*)(C + (size_t)r0     * N + c) = v0;
            *(float2*)(C + (size_t)(r0+8) * N + c) = v1;
        }
    }
#undef LOAD_STAGE
}

// ---------------- GRU pointwise updates (float4 vectorized) ----------------
__device__ __forceinline__ void gru_elem(float xr, float xz, float xn,
                                         float gr, float gz, float gn,
                                         float h, float& hn_out)
{
    float r = 1.f / (1.f + expf(-(xr + gr)));
    float z = 1.f / (1.f + expf(-(xz + gz)));
    float n = tanhf(xn + r * gn);
    hn_out = (1.f - z) * n + z * h;
}

__global__ void k_pw0(const float* __restrict__ bih, const float* __restrict__ bhh, int t) {
    if (t >= d_T[0]) return;
    int i4 = blockIdx.x * blockDim.x + threadIdx.x;
    if (i4 >= BSZ*HSZ/4) return;
    int i = i4 << 2;
    int b = i >> 9, j = i & (HSZ-1);
    int base = b*H3 + j;
    float4 ar = *(const float4*)(d_A0 + base);
    float4 az = *(const float4*)(d_A0 + base + HSZ);
    float4 an = *(const float4*)(d_A0 + base + 2*HSZ);
    float4 gr = *(const float4*)(d_G0 + base);
    float4 gz = *(const float4*)(d_G0 + base + HSZ);
    float4 gn = *(const float4*)(d_G0 + base + 2*HSZ);
    float4 h  = *(const float4*)(d_h0 + i);
    float4 bir = *(const float4*)(bih + j);
    float4 biz = *(const float4*)(bih + j + HSZ);
    float4 bin = *(const float4*)(bih + j + 2*HSZ);
    float4 bhr = *(const float4*)(bhh + j);
    float4 bhz = *(const float4*)(bhh + j + HSZ);
    float4 bhn = *(const float4*)(bhh + j + 2*HSZ);

    float hn[4];
    const float* pxr=(const float*)&ar; const float* pxz=(const float*)&az; const float* pxn=(const float*)&an;
    const float* pgr=(const float*)&gr; const float* pgz=(const float*)&gz; const float* pgn=(const float*)&gn;
    const float* ph =(const float*)&h;
    const float* pir=(const float*)&bir; const float* piz=(const float*)&biz; const float* pin=(const float*)&bin;
    const float* phr=(const float*)&bhr; const float* phz=(const float*)&bhz; const float* phn=(const float*)&bhn;
#pragma unroll
    for (int e = 0; e < 4; e++)
        gru_elem(pxr[e]+pir[e], pxz[e]+piz[e], pxn[e]+pin[e],
                 pgr[e]+phr[e], pgz[e]+phz[e], pgn[e]+phn[e], ph[e], hn[e]);

    *(float4*)(d_h0 + i) = make_float4(hn[0], hn[1], hn[2], hn[3]);
    __half2 p0 = __floats2half2_rn(hn[0], hn[1]);
    __half2 p1 = __floats2half2_rn(hn[2], hn[3]);
    ((__half2*)(d_h0h + i))[0] = p0;
    ((__half2*)(d_h0h + i))[1] = p1;
}

__global__ void k_pw1(const float* __restrict__ bih, const float* __restrict__ bhh, int t) {
    if (t >= d_T[0]) return;
    int i4 = blockIdx.x * blockDim.x + threadIdx.x;
    if (i4 >= BSZ*HSZ/4) return;
    int i = i4 << 2;
    int b = i >> 9, j = i & (HSZ-1);
    int base = b*H3 + j;
    float4 ar = *(const float4*)(d_A1 + base);
    float4 az = *(const float4*)(d_A1 + base + HSZ);
    float4 an = *(const float4*)(d_A1 + base + 2*HSZ);
    float4 gr = *(const float4*)(d_G1 + base);
    float4 gz = *(const float4*)(d_G1 + base + HSZ);
    float4 gn = *(const float4*)(d_G1 + base + 2*HSZ);
    float4 h  = *(const float4*)(d_h1 + i);
    float4 bir = *(const float4*)(bih + j);
    float4 biz = *(const float4*)(bih + j + HSZ);
    float4 bin = *(const float4*)(bih + j + 2*HSZ);
    float4 bhr = *(const float4*)(bhh + j);
    float4 bhz = *(const float4*)(bhh + j + HSZ);
    float4 bhn = *(const float4*)(bhh + j + 2*HSZ);

    float hn[4];
    const float* pxr=(const float*)&ar; const float* pxz=(const float*)&az; const float* pxn=(const float*)&an;
    const float* pgr=(const float*)&gr; const float* pgz=(const float*)&gz; const float* pgn=(const float*)&gn;
    const float* ph =(const float*)&h;
    const float* pir=(const float*)&bir; const float* piz=(const float*)&biz; const float* pin=(const float*)&bin;
    const float* phr=(const float*)&bhr; const float* phz=(const float*)&bhz; const float* phn=(const float*)&bhn;
#pragma unroll
    for (int e = 0; e < 4; e++)
        gru_elem(pxr[e]+pir[e], pxz[e]+piz[e], pxn[e]+pin[e],
                 pgr[e]+phr[e], pgz[e]+phz[e], pgn[e]+phn[e], ph[e], hn[e]);

    *(float4*)(d_h1 + i) = make_float4(hn[0], hn[1], hn[2], hn[3]);
    __half2 p0 = __floats2half2_rn(hn[0], hn[1]);
    __half2 p1 = __floats2half2_rn(hn[2], hn[3]);
    ((__half2*)(d_h1h + i))[0] = p0;
    ((__half2*)(d_h1h + i))[1] = p1;
    __half* y = d_Y1h + (size_t)t * (BSZ*HSZ) + i;
    ((__half2*)y)[0] = p0;
    ((__half2*)y)[1] = p1;
}

// ---------------- host launch ----------------
static void launch_gemm1(const __half* A, const __half* W, float* C,
                         int M, int N, int K, const int* aoff, const float* bias,
                         int t, int chk)
{
    dim3 grid(N / BN, M / BM, 1);
    gemm_fp16<<<grid, 256, SMEM_BYTES>>>(A, W, C, A, W, C, M, N, K, aoff, bias, t, chk);
}

extern "C" void kernel_launch(void* const* d_in, const int* in_sizes, int n_in,
                              void* d_out, int out_size)
{
    const float* x    = (const float*)d_in[0];
    const float* Wih0 = (const float*)d_in[1];
    const float* Whh0 = (const float*)d_in[2];
    const float* bih0 = (const float*)d_in[3];
    const float* bhh0 = (const float*)d_in[4];
    const float* Wih1 = (const float*)d_in[5];
    const float* Whh1 = (const float*)d_in[6];
    const float* bih1 = (const float*)d_in[7];
    const float* bhh1 = (const float*)d_in[8];
    const float* Wout = (const float*)d_in[9];
    const float* bout = (const float*)d_in[10];
    const int*   psi  = (const int*)d_in[11];
    float* out = (float*)d_out;

    cudaFuncSetAttribute(gemm_fp16, cudaFuncAttributeMaxDynamicSharedMemorySize, SMEM_BYTES);

    __half *p_h0h, *p_h1h, *p_Y1h, *p_xh, *p_Wih0h, *p_Whh0h, *p_Wih1h, *p_Whh1h, *p_Wouth;
    float *p_A0, *p_G0, *p_G1, *p_A1;
    int *p_rowoff;
    cudaGetSymbolAddress((void**)&p_h0h,   d_h0h);
    cudaGetSymbolAddress((void**)&p_h1h,   d_h1h);
    cudaGetSymbolAddress((void**)&p_Y1h,   d_Y1h);
    cudaGetSymbolAddress((void**)&p_xh,    d_xh);
    cudaGetSymbolAddress((void**)&p_Wih0h, d_Wih0h);
    cudaGetSymbolAddress((void**)&p_Whh0h, d_Whh0h);
    cudaGetSymbolAddress((void**)&p_Wih1h, d_Wih1h);
    cudaGetSymbolAddress((void**)&p_Whh1h, d_Whh1h);
    cudaGetSymbolAddress((void**)&p_Wouth, d_Wouth);
    cudaGetSymbolAddress((void**)&p_A0,    d_A0);
    cudaGetSymbolAddress((void**)&p_G0,    d_G0);
    cudaGetSymbolAddress((void**)&p_G1,    d_G1);
    cudaGetSymbolAddress((void**)&p_A1,    d_A1);
    cudaGetSymbolAddress((void**)&p_rowoff, d_rowoff);

    const int PW4 = (BSZ*HSZ/4 + 255) / 256;
    const int PWI = (BSZ*HSZ + 255) / 256;

    k_init <<<PWI, 256>>>();
    k_first<<<(NSZ + 255) / 256, 256>>>(psi);
    k_rank <<<(NSZ + 255) / 256, 256>>>(psi);

    // convert weights and x to fp16, once per launch
    k_tohalf<<<(BSZ*INSZ/4  + 255)/256, 256>>>(x,    p_xh,    BSZ*INSZ/4);
    k_tohalf<<<(H3*INSZ/4   + 255)/256, 256>>>(Wih0, p_Wih0h, H3*INSZ/4);
    k_tohalf<<<(H3*HSZ/4    + 255)/256, 256>>>(Whh0, p_Whh0h, H3*HSZ/4);
    k_tohalf<<<(H3*HSZ/4    + 255)/256, 256>>>(Wih1, p_Wih1h, H3*HSZ/4);
    k_tohalf<<<(H3*HSZ/4    + 255)/256, 256>>>(Whh1, p_Whh1h, H3*HSZ/4);
    k_tohalf<<<(OUTSZ*HSZ/4 + 255)/256, 256>>>(Wout, p_Wouth, OUTSZ*HSZ/4);

    // layer-0 input projection, computed once (timestep input is constant)
    launch_gemm1(p_xh, p_Wih0h, p_A0, BSZ, H3, INSZ, nullptr, nullptr, 0, 0);

    for (int t = 0; t < T_MAX; t++) {
        // two independent recurrent projections in ONE launch (gridDim.z = 2)
        {
            dim3 grid(H3 / BN, BSZ / BM, 2);
            gemm_fp16<<<grid, 256, SMEM_BYTES>>>(
                p_h0h, p_Whh0h, p_G0,
                p_h1h, p_Whh1h, p_G1,
                BSZ, H3, HSZ, nullptr, nullptr, t, 1);
        }
        k_pw0<<<PW4, 256>>>(bih0, bhh0, t);
        launch_gemm1(p_h0h, p_Wih1h, p_A1, BSZ, H3, HSZ, nullptr, nullptr, t, 1);
        k_pw1<<<PW4, 256>>>(bih1, bhh1, t);
    }

    // gathered output GEMM: out[N, OUT] = Y1h[rowoff[j]] . Wout^T + bout
    launch_gemm1(p_Y1h, p_Wouth, out, NSZ, OUTSZ, HSZ, p_rowoff, bout, 0, 0);

    (void)in_sizes; (void)n_in; (void)out_size;
}

// round 6
// speedup vs baseline: 3.1958x; 1.0632x over previous
#include <cuda_runtime.h>
#include <cuda_fp16.h>
#include <math.h>
#include <stdint.h>

// Problem constants
#define BSZ   2048
#define INSZ  512
#define HSZ   512
#define OUTSZ 256
#define NSZ   32768
#define H3    (3*HSZ)
#define T_MAX 48

#define BM 128
#define BN 128
#define BKH 64                              // k per smem tile (halfs) = 128B rows
#define ROWU32 32                           // u32 words per smem row (128B)
#define STAGE_U32 (2*BM*ROWU32)             // A tile + W tile = 8192 u32 = 32KB
#define STAGE_BYTES (STAGE_U32*4)
#define STAGES 3
#define SMEM_BYTES (STAGES*STAGE_BYTES)     // 98304 B

// ---------------- device scratch (static, no allocations) ----------------
__device__ float  d_h0 [BSZ*HSZ];
__device__ float  d_h1 [BSZ*HSZ];
__device__ __half d_h0h[BSZ*HSZ];
__device__ __half d_h1h[BSZ*HSZ];
__device__ float  d_A0 [BSZ*H3];
__device__ float  d_G0 [BSZ*H3];
__device__ float  d_G1 [BSZ*H3];
__device__ float  d_A1 [BSZ*H3];
__device__ __half d_Y1h[(size_t)T_MAX*BSZ*HSZ];
__device__ __half d_xh   [BSZ*INSZ];
__device__ __half d_Wih0h[H3*INSZ];
__device__ __half d_Whh0h[H3*HSZ];
__device__ __half d_Wih1h[H3*HSZ];
__device__ __half d_Whh1h[H3*HSZ];
__device__ __half d_Wouth[OUTSZ*HSZ];
__device__ int    d_first[BSZ];
__device__ int    d_rowoff[NSZ];
__device__ int    d_T[1];

// ---------------- setup kernels (ordered so GEMM = launch index 5) ----------------
// launch 0: init state + first-occurrence markers
__global__ void k_init_first(const int* __restrict__ psi) {
    int i = blockIdx.x * blockDim.x + threadIdx.x;
    if (i == 0) d_T[0] = 0;
    if (i < BSZ*HSZ) {
        d_h0[i]=0.f; d_h1[i]=0.f;
        d_h0h[i]=__float2half(0.f); d_h1h[i]=__float2half(0.f);
    }
    if (i < NSZ) {
        if (i == 0 || psi[i] != psi[i-1]) d_first[psi[i]] = i;
    }
}

// launch 1: ranks + T
__global__ void k_rank(const int* __restrict__ psi) {
    int j = blockIdx.x * blockDim.x + threadIdx.x;
    if (j >= NSZ) return;
    int v = psi[j];
    int r = j - d_first[v];
    d_rowoff[j] = r * (BSZ*HSZ) + v * HSZ;   // element offset of row start
    atomicMax(&d_T[0], r + 1);
}

__device__ __forceinline__ void conv4(const float* src, __half* dst, int i) {
    float4 v = *(const float4*)(src + i);
    ((__half2*)(dst + i))[0] = __floats2half2_rn(v.x, v.y);
    ((__half2*)(dst + i))[1] = __floats2half2_rn(v.z, v.w);
}

// launch 2: convert x, Wih0
__global__ void k_convA(const float* __restrict__ x, const float* __restrict__ w0) {
    int i = (blockIdx.x * blockDim.x + threadIdx.x) << 2;
    if (i < BSZ*INSZ) conv4(x, d_xh, i);
    if (i < H3*INSZ)  conv4(w0, d_Wih0h, i);
}

// launch 3: convert Whh0, Wih1, Whh1, Wout
__global__ void k_convB(const float* __restrict__ whh0, const float* __restrict__ wih1,
                        const float* __restrict__ whh1, const float* __restrict__ wout) {
    int i = (blockIdx.x * blockDim.x + threadIdx.x) << 2;
    if (i < H3*HSZ) {
        conv4(whh0, d_Whh0h, i);
        conv4(wih1, d_Wih1h, i);
        conv4(whh1, d_Whh1h, i);
    }
    if (i < OUTSZ*HSZ) conv4(wout, d_Wouth, i);
}

// ---------------- fp16 mma GEMM, cp.async 3-stage + ldmatrix ----------------
// C[M,N] = A[M,K] * W[N,K]^T (+bias), fp16 in, fp32 accum/out.
// A rows optionally gathered via a_off. blockIdx.z picks operand set.
__global__ __launch_bounds__(256, 2)
void gemm_fp16(const __half* __restrict__ Aa, const __half* __restrict__ Wa, float* __restrict__ Ca,
               const __half* __restrict__ Ab, const __half* __restrict__ Wb, float* __restrict__ Cb,
               int M, int N, int K,
               const int* __restrict__ a_off, const float* __restrict__ bias,
               int t_step, int check_T)
{
    if (check_T && t_step >= d_T[0]) return;

    const __half* A = blockIdx.z ? Ab : Aa;
    const __half* W = blockIdx.z ? Wb : Wa;
    float*        C = blockIdx.z ? Cb : Ca;

    extern __shared__ uint32_t sm[];
    const uint32_t smaddr = (uint32_t)__cvta_generic_to_shared(sm);

    const int tid  = threadIdx.x;
    const int lane = tid & 31;
    const int warp = tid >> 5;
    const int wm   = warp >> 2;   // 0..1
    const int wn   = warp & 3;    // 0..3
    const int g    = lane >> 2;   // 0..7
    const int q    = lane & 3;    // 0..3

    const int row0 = blockIdx.y * BM;
    const int col0 = blockIdx.x * BN;

    // ---- loader mapping: thread t loads row t>>1, 16B-groups (t&1)*4 .. +3 ----
    const int lm   = tid >> 1;
    const int lkg0 = (tid & 1) * 4;

    long arow = a_off ? (long)a_off[row0 + lm] : (long)(row0 + lm) * K;
    const __half* agp = A + arow;
    const __half* wgp = W + (long)(col0 + lm) * K;

    uint32_t soffB[4];
#pragma unroll
    for (int j = 0; j < 4; j++)
        soffB[j] = (uint32_t)(lm * 128 + (((lkg0 + j) ^ (lm & 7)) << 4));

#define LOAD_STAGE(st, kt) do {                                              \
        uint32_t dA = smaddr + (st)*STAGE_BYTES;                             \
        uint32_t dW = dA + BM*128;                                           \
        const __half* ga = agp + (size_t)(kt)*BKH;                           \
        const __half* gw = wgp + (size_t)(kt)*BKH;                           \
        _Pragma("unroll")                                                    \
        for (int j = 0; j < 4; j++) {                                        \
            asm volatile("cp.async.cg.shared.global [%0], [%1], 16;"         \
                         :: "r"(dA + soffB[j]), "l"(ga + (lkg0 + j)*8));     \
            asm volatile("cp.async.cg.shared.global [%0], [%1], 16;"         \
                         :: "r"(dW + soffB[j]), "l"(gw + (lkg0 + j)*8));     \
        }                                                                    \
    } while (0)

    float acc[4][4][4];
#pragma unroll
    for (int a = 0; a < 4; a++)
#pragma unroll
        for (int b = 0; b < 4; b++)
#pragma unroll
            for (int c = 0; c < 4; c++) acc[a][b][c] = 0.f;

    const int KT = K / BKH;

#pragma unroll
    for (int s = 0; s < STAGES-1; s++) {
        LOAD_STAGE(s, s);
        asm volatile("cp.async.commit_group;" ::: "memory");
    }

    // ---- ldmatrix per-thread address components ----
    // A x4: lanes 0-15 -> rows mrow+(lane&15) (k-lo group), lanes 16-31 same rows (k-hi)
    // W x4: lanes 0-7 rows ncol+(lane&7) grp 4kp+0; 8-15 grp+1; 16-23 grp+2; 24-31 grp+3
    const uint32_t a_row15 = lane & 15;
    const uint32_t a_hi    = lane >> 4;        // 0/1: k-lo / k-hi group
    const uint32_t x7      = lane & 7;
    const uint32_t w_hi    = lane >> 3;        // 0..3

    uint32_t aRowOff[4], wRowOff[4];
#pragma unroll
    for (int mi = 0; mi < 4; mi++)
        aRowOff[mi] = (uint32_t)((wm*64 + mi*16 + a_row15) * 128);
#pragma unroll
    for (int ni = 0; ni < 4; ni++)
        wRowOff[ni] = (uint32_t)((BM*128) + (wn*32 + ni*8 + x7) * 128);

    for (int kt = 0; kt < KT; kt++) {
        asm volatile("cp.async.wait_group %0;" :: "n"(STAGES-2) : "memory");
        __syncthreads();

        int ktn = kt + STAGES - 1;
        if (ktn < KT) LOAD_STAGE(ktn % STAGES, ktn);
        asm volatile("cp.async.commit_group;" ::: "memory");

        const uint32_t sbase = smaddr + (kt % STAGES)*STAGE_BYTES;

#pragma unroll
        for (int kp = 0; kp < 2; kp++) {           // k16 pairs
            // W: one x4 per ni covers k-steps 2kp and 2kp+1
            uint32_t wq[4][4];
            const uint32_t wsw = ((4*kp + w_hi) ^ x7) << 4;
#pragma unroll
            for (int ni = 0; ni < 4; ni++) {
                uint32_t addr = sbase + wRowOff[ni] + wsw;
                asm volatile("ldmatrix.sync.aligned.m8n8.x4.shared.b16 {%0,%1,%2,%3}, [%4];"
                    : "=r"(wq[ni][0]), "=r"(wq[ni][1]), "=r"(wq[ni][2]), "=r"(wq[ni][3])
                    : "r"(addr));
            }
#pragma unroll
            for (int kk2 = 0; kk2 < 2; kk2++) {
                const int kk = 2*kp + kk2;
                const uint32_t asw = ((2*kk + a_hi) ^ x7) << 4;
                uint32_t af[4][4];
#pragma unroll
                for (int mi = 0; mi < 4; mi++) {
                    uint32_t addr = sbase + aRowOff[mi] + asw;
                    asm volatile("ldmatrix.sync.aligned.m8n8.x4.shared.b16 {%0,%1,%2,%3}, [%4];"
                        : "=r"(af[mi][0]), "=r"(af[mi][1]), "=r"(af[mi][2]), "=r"(af[mi][3])
                        : "r"(addr));
                }
#pragma unroll
                for (int mi = 0; mi < 4; mi++)
#pragma unroll
                    for (int ni = 0; ni < 4; ni++)
                        asm volatile(
                            "mma.sync.aligned.m16n8k16.row.col.f32.f16.f16.f32 "
                            "{%0,%1,%2,%3}, {%4,%5,%6,%7}, {%8,%9}, {%0,%1,%2,%3};"
                            : "+f"(acc[mi][ni][0]), "+f"(acc[mi][ni][1]),
                              "+f"(acc[mi][ni][2]), "+f"(acc[mi][ni][3])
                            : "r"(af[mi][0]), "r"(af[mi][1]), "r"(af[mi][2]), "r"(af[mi][3]),
                              "r"(wq[ni][2*kk2]), "r"(wq[ni][2*kk2+1]));
            }
        }
    }

    // epilogue
#pragma unroll
    for (int mi = 0; mi < 4; mi++) {
        int r0 = row0 + wm*64 + mi*16 + g;
#pragma unroll
        for (int ni = 0; ni < 4; ni++) {
            int c = col0 + wn*32 + ni*8 + 2*q;
            float b0 = 0.f, b1 = 0.f;
            if (bias) { b0 = bias[c]; b1 = bias[c+1]; }
            float2 v0 = make_float2(acc[mi][ni][0] + b0, acc[mi][ni][1] + b1);
            float2 v1 = make_float2(acc[mi][ni][2] + b0, acc[mi][ni][3] + b1);
            *(float2*)(C + (size_t)r0     * N + c) = v0;
            *(float2*)(C + (size_t)(r0+8) * N + c) = v1;
        }
    }
#undef LOAD_STAGE
}

// ---------------- GRU pointwise updates (float4 vectorized) ----------------
__device__ __forceinline__ void gru_elem(float xr, float xz, float xn,
                                         float gr, float gz, float gn,
                                         float h, float& hn_out)
{
    float r = 1.f / (1.f + expf(-(xr + gr)));
    float z = 1.f / (1.f + expf(-(xz + gz)));
    float n = tanhf(xn + r * gn);
    hn_out = (1.f - z) * n + z * h;
}

__global__ void k_pw0(const float* __restrict__ bih, const float* __restrict__ bhh, int t) {
    if (t >= d_T[0]) return;
    int i4 = blockIdx.x * blockDim.x + threadIdx.x;
    if (i4 >= BSZ*HSZ/4) return;
    int i = i4 << 2;
    int b = i >> 9, j = i & (HSZ-1);
    int base = b*H3 + j;
    float4 ar = *(const float4*)(d_A0 + base);
    float4 az = *(const float4*)(d_A0 + base + HSZ);
    float4 an = *(const float4*)(d_A0 + base + 2*HSZ);
    float4 gr = *(const float4*)(d_G0 + base);
    float4 gz = *(const float4*)(d_G0 + base + HSZ);
    float4 gn = *(const float4*)(d_G0 + base + 2*HSZ);
    float4 h  = *(const float4*)(d_h0 + i);
    float4 bir = *(const float4*)(bih + j);
    float4 biz = *(const float4*)(bih + j + HSZ);
    float4 bin = *(const float4*)(bih + j + 2*HSZ);
    float4 bhr = *(const float4*)(bhh + j);
    float4 bhz = *(const float4*)(bhh + j + HSZ);
    float4 bhn = *(const float4*)(bhh + j + 2*HSZ);

    float hn[4];
    const float* pxr=(const float*)&ar; const float* pxz=(const float*)&az; const float* pxn=(const float*)&an;
    const float* pgr=(const float*)&gr; const float* pgz=(const float*)&gz; const float* pgn=(const float*)&gn;
    const float* ph =(const float*)&h;
    const float* pir=(const float*)&bir; const float* piz=(const float*)&biz; const float* pin=(const float*)&bin;
    const float* phr=(const float*)&bhr; const float* phz=(const float*)&bhz; const float* phn=(const float*)&bhn;
#pragma unroll
    for (int e = 0; e < 4; e++)
        gru_elem(pxr[e]+pir[e], pxz[e]+piz[e], pxn[e]+pin[e],
                 pgr[e]+phr[e], pgz[e]+phz[e], pgn[e]+phn[e], ph[e], hn[e]);

    *(float4*)(d_h0 + i) = make_float4(hn[0], hn[1], hn[2], hn[3]);
    ((__half2*)(d_h0h + i))[0] = __floats2half2_rn(hn[0], hn[1]);
    ((__half2*)(d_h0h + i))[1] = __floats2half2_rn(hn[2], hn[3]);
}

__global__ void k_pw1(const float* __restrict__ bih, const float* __restrict__ bhh, int t) {
    if (t >= d_T[0]) return;
    int i4 = blockIdx.x * blockDim.x + threadIdx.x;
    if (i4 >= BSZ*HSZ/4) return;
    int i = i4 << 2;
    int b = i >> 9, j = i & (HSZ-1);
    int base = b*H3 + j;
    float4 ar = *(const float4*)(d_A1 + base);
    float4 az = *(const float4*)(d_A1 + base + HSZ);
    float4 an = *(const float4*)(d_A1 + base + 2*HSZ);
    float4 gr = *(const float4*)(d_G1 + base);
    float4 gz = *(const float4*)(d_G1 + base + HSZ);
    float4 gn = *(const float4*)(d_G1 + base + 2*HSZ);
    float4 h  = *(const float4*)(d_h1 + i);
    float4 bir = *(const float4*)(bih + j);
    float4 biz = *(const float4*)(bih + j + HSZ);
    float4 bin = *(const float4*)(bih + j + 2*HSZ);
    float4 bhr = *(const float4*)(bhh + j);
    float4 bhz = *(const float4*)(bhh + j + HSZ);
    float4 bhn = *(const float4*)(bhh + j + 2*HSZ);

    float hn[4];
    const float* pxr=(const float*)&ar; const float* pxz=(const float*)&az; const float* pxn=(const float*)&an;
    const float* pgr=(const float*)&gr; const float* pgz=(const float*)&gz; const float* pgn=(const float*)&gn;
    const float* ph =(const float*)&h;
    const float* pir=(const float*)&bir; const float* piz=(const float*)&biz; const float* pin=(const float*)&bin;
    const float* phr=(const float*)&bhr; const float* phz=(const float*)&bhz; const float* phn=(const float*)&bhn;
#pragma unroll
    for (int e = 0; e < 4; e++)
        gru_elem(pxr[e]+pir[e], pxz[e]+piz[e], pxn[e]+pin[e],
                 pgr[e]+phr[e], pgz[e]+phz[e], pgn[e]+phn[e], ph[e], hn[e]);

    *(float4*)(d_h1 + i) = make_float4(hn[0], hn[1], hn[2], hn[3]);
    __half2 p0 = __floats2half2_rn(hn[0], hn[1]);
    __half2 p1 = __floats2half2_rn(hn[2], hn[3]);
    ((__half2*)(d_h1h + i))[0] = p0;
    ((__half2*)(d_h1h + i))[1] = p1;
    __half* y = d_Y1h + (size_t)t * (BSZ*HSZ) + i;
    ((__half2*)y)[0] = p0;
    ((__half2*)y)[1] = p1;
}

// ---------------- host launch ----------------
static void launch_gemm1(const __half* A, const __half* W, float* C,
                         int M, int N, int K, const int* aoff, const float* bias,
                         int t, int chk)
{
    dim3 grid(N / BN, M / BM, 1);
    gemm_fp16<<<grid, 256, SMEM_BYTES>>>(A, W, C, A, W, C, M, N, K, aoff, bias, t, chk);
}

extern "C" void kernel_launch(void* const* d_in, const int* in_sizes, int n_in,
                              void* d_out, int out_size)
{
    const float* x    = (const float*)d_in[0];
    const float* Wih0 = (const float*)d_in[1];
    const float* Whh0 = (const float*)d_in[2];
    const float* bih0 = (const float*)d_in[3];
    const float* bhh0 = (const float*)d_in[4];
    const float* Wih1 = (const float*)d_in[5];
    const float* Whh1 = (const float*)d_in[6];
    const float* bih1 = (const float*)d_in[7];
    const float* bhh1 = (const float*)d_in[8];
    const float* Wout = (const float*)d_in[9];
    const float* bout = (const float*)d_in[10];
    const int*   psi  = (const int*)d_in[11];
    float* out = (float*)d_out;

    cudaFuncSetAttribute(gemm_fp16, cudaFuncAttributeMaxDynamicSharedMemorySize, SMEM_BYTES);

    __half *p_h0h, *p_h1h, *p_Y1h, *p_xh, *p_Wih0h, *p_Whh0h, *p_Wih1h, *p_Whh1h, *p_Wouth;
    float *p_A0, *p_G0, *p_G1, *p_A1;
    int *p_rowoff;
    cudaGetSymbolAddress((void**)&p_h0h,   d_h0h);
    cudaGetSymbolAddress((void**)&p_h1h,   d_h1h);
    cudaGetSymbolAddress((void**)&p_Y1h,   d_Y1h);
    cudaGetSymbolAddress((void**)&p_xh,    d_xh);
    cudaGetSymbolAddress((void**)&p_Wih0h, d_Wih0h);
    cudaGetSymbolAddress((void**)&p_Whh0h, d_Whh0h);
    cudaGetSymbolAddress((void**)&p_Wih1h, d_Wih1h);
    cudaGetSymbolAddress((void**)&p_Whh1h, d_Whh1h);
    cudaGetSymbolAddress((void**)&p_Wouth, d_Wouth);
    cudaGetSymbolAddress((void**)&p_A0,    d_A0);
    cudaGetSymbolAddress((void**)&p_G0,    d_G0);
    cudaGetSymbolAddress((void**)&p_G1,    d_G1);
    cudaGetSymbolAddress((void**)&p_A1,    d_A1);
    cudaGetSymbolAddress((void**)&p_rowoff, d_rowoff);

    const int PW4 = (BSZ*HSZ/4 + 255) / 256;
    const int PWI = (BSZ*HSZ + 255) / 256;

    // launches 0..3 (setup), 4 (A0 GEMM), 5 (merged G GEMM, t=0) -> ncu -s 5 target
    k_init_first<<<PWI, 256>>>(psi);                       // 0
    k_rank<<<(NSZ + 255) / 256, 256>>>(psi);               // 1
    k_convA<<<(BSZ*INSZ/4 + 255)/256, 256>>>(x, Wih0);     // 2
    k_convB<<<(H3*HSZ/4   + 255)/256, 256>>>(Whh0, Wih1, Whh1, Wout); // 3
    launch_gemm1(p_xh, p_Wih0h, p_A0, BSZ, H3, INSZ, nullptr, nullptr, 0, 0); // 4

    for (int t = 0; t < T_MAX; t++) {
        {
            dim3 grid(H3 / BN, BSZ / BM, 2);
            gemm_fp16<<<grid, 256, SMEM_BYTES>>>(
                p_h0h, p_Whh0h, p_G0,
                p_h1h, p_Whh1h, p_G1,
                BSZ, H3, HSZ, nullptr, nullptr, t, 1);
        }
        k_pw0<<<PW4, 256>>>(bih0, bhh0, t);
        launch_gemm1(p_h0h, p_Wih1h, p_A1, BSZ, H3, HSZ, nullptr, nullptr, t, 1);
        k_pw1<<<PW4, 256>>>(bih1, bhh1, t);
    }

    // gathered output GEMM: out[N, OUT] = Y1h[rowoff[j]] . Wout^T + bout
    launch_gemm1(p_Y1h, p_Wouth, out, NSZ, OUTSZ, HSZ, p_rowoff, bout, 0, 0);

    (void)in_sizes; (void)n_in; (void)out_size;
}